// round 4
// baseline (speedup 1.0000x reference)
#include <cuda_runtime.h>

// LocalAttention fused kernel for GB300 (sm_103a).
//
// Reference collapses to:
//   T[b,l,j]   = dot(x[b,l,:], W[j,:])   for 18 weight rows
//                 (rows 0-2: aw3, 3-7: aw5, 8-14: aw7, 15: cw3, 16: cw5, 17: cw7)
//   s_k[b,l]   = sum_j T[b, l - p_k + j, jcol_k(j)]   (zero outside [0,L))
//   out_k[b,l] = tanh( sigmoid(s_k + ab_k) * T[b,l,dcol_k] + cb_k )
//
// One fused kernel: per block, compute T for 256 consecutive l (250 outputs
// + 3 halo each side), stash in shared, combine in-block.
// Packed fp32x2 FMAs (Blackwell) halve FMA instruction count.

#define FMA2(d, a, b, c) \
    asm("fma.rn.f32x2 %0, %1, %2, %3;" : "=l"(d) : "l"(a), "l"(b), "l"(c))

__device__ __forceinline__ unsigned long long pk2(float lo, float hi) {
    unsigned long long r;
    asm("mov.b64 %0, {%1, %2};" : "=l"(r) : "f"(lo), "f"(hi));
    return r;
}

__device__ __forceinline__ float unpk_sum(unsigned long long v) {
    float lo, hi;
    asm("mov.b64 {%0, %1}, %2;" : "=f"(lo), "=f"(hi) : "l"(v));
    return lo + hi;
}

__device__ __forceinline__ float sigm(float v) {
    return 1.0f / (1.0f + __expf(-v));
}

constexpr int Lc = 500;
constexpr int Ec = 300;
constexpr int E4 = Ec / 4;        // 75 float4 per row
constexpr int TL = 250;           // outputs per block
constexpr int POS = 256;          // computed positions per block (TL + 6 halo)
constexpr int NJ = 18;            // weight rows
constexpr int TSTRIDE = 19;       // padded T stride (bank decorrelation)

__global__ __launch_bounds__(128, 4)
void la_fused_kernel(const float* __restrict__ x,
                     const float* __restrict__ aw3, const float* __restrict__ ab3,
                     const float* __restrict__ cw3, const float* __restrict__ cb3,
                     const float* __restrict__ aw5, const float* __restrict__ ab5,
                     const float* __restrict__ cw5, const float* __restrict__ cb5,
                     const float* __restrict__ aw7, const float* __restrict__ ab7,
                     const float* __restrict__ cw7, const float* __restrict__ cb7,
                     float* __restrict__ out, int Ltot /* = B*L */)
{
    __shared__ __align__(16) float ws[NJ * Ec];      // 21600 B weights
    __shared__ float Tsh[POS * TSTRIDE];             // 19456 B T values

    const int tid  = threadIdx.x;
    const int b    = blockIdx.y;
    const int tile = blockIdx.x;
    const int l_base = tile * TL - 3;

    // ---- stage the 18 weight rows into shared (broadcast source for LDS.128) ----
    for (int i = tid; i < 3 * Ec; i += 128) ws[i]          = aw3[i];
    for (int i = tid; i < 5 * Ec; i += 128) ws[3 * Ec + i] = aw5[i];
    for (int i = tid; i < 7 * Ec; i += 128) ws[8 * Ec + i] = aw7[i];
    for (int i = tid; i < Ec; i += 128) {
        ws[15 * Ec + i] = cw3[i];
        ws[16 * Ec + i] = cw5[i];
        ws[17 * Ec + i] = cw7[i];
    }
    __syncthreads();

    // ---- each thread owns two l-positions: pos = tid and tid+128 ----
    const int posA = tid, posB = tid + 128;
    const int lA = l_base + posA;
    const int lB = l_base + posB;
    const bool vA = (lA >= 0) && (lA < Lc);
    const bool vB = (lB >= 0) && (lB < Lc);
    const float4* pA = (const float4*)(x + ((size_t)b * Lc + (vA ? lA : 0)) * Ec);
    const float4* pB = (const float4*)(x + ((size_t)b * Lc + (vB ? lB : 0)) * Ec);
    const float4* w4 = (const float4*)ws;

    unsigned long long accA[NJ], accB[NJ];
    #pragma unroll
    for (int j = 0; j < NJ; ++j) { accA[j] = 0ull; accB[j] = 0ull; }

    const float4 zero4 = make_float4(0.f, 0.f, 0.f, 0.f);

    // ---- main reduction: 18 dot products over E=300 for both l-positions ----
    #pragma unroll 2
    for (int it = 0; it < E4; ++it) {
        float4 xa = vA ? pA[it] : zero4;
        float4 xb = vB ? pB[it] : zero4;
        unsigned long long xa0 = pk2(xa.x, xa.y), xa1 = pk2(xa.z, xa.w);
        unsigned long long xb0 = pk2(xb.x, xb.y), xb1 = pk2(xb.z, xb.w);
        #pragma unroll
        for (int j = 0; j < NJ; ++j) {
            float4 w = w4[j * E4 + it];
            unsigned long long w0 = pk2(w.x, w.y), w1 = pk2(w.z, w.w);
            FMA2(accA[j], xa0, w0, accA[j]);
            FMA2(accA[j], xa1, w1, accA[j]);
            FMA2(accB[j], xb0, w0, accB[j]);
            FMA2(accB[j], xb1, w1, accB[j]);
        }
    }

    // ---- write T to shared ----
    #pragma unroll
    for (int j = 0; j < NJ; ++j) {
        Tsh[posA * TSTRIDE + j] = unpk_sum(accA[j]);
        Tsh[posB * TSTRIDE + j] = unpk_sum(accB[j]);
    }
    __syncthreads();

    // ---- epilogue: shifted sums + sigmoid gate + tanh, for interior positions ----
    const float sab3 = ab3[0], scb3 = cb3[0];
    const float sab5 = ab5[0], scb5 = cb5[0];
    const float sab7 = ab7[0], scb7 = cb7[0];

    #pragma unroll
    for (int half = 0; half < 2; ++half) {
        const int pos = tid + half * 128;
        if (pos >= 3 && pos <= 252) {
            const float* T0 = &Tsh[pos * TSTRIDE];
            // k=3, p=1: s = t0[l-1] + t1[l] + t2[l+1]
            float s3 = Tsh[(pos - 1) * TSTRIDE + 0] + T0[1]
                     + Tsh[(pos + 1) * TSTRIDE + 2];
            // k=5, p=2
            float s5 = 0.f;
            #pragma unroll
            for (int j = 0; j < 5; ++j) s5 += Tsh[(pos - 2 + j) * TSTRIDE + 3 + j];
            // k=7, p=3
            float s7 = 0.f;
            #pragma unroll
            for (int j = 0; j < 7; ++j) s7 += Tsh[(pos - 3 + j) * TSTRIDE + 8 + j];

            float o3 = tanhf(sigm(s3 + sab3) * T0[15] + scb3);
            float o5 = tanhf(sigm(s5 + sab5) * T0[16] + scb5);
            float o7 = tanhf(sigm(s7 + sab7) * T0[17] + scb7);

            const int l_out = l_base + pos;                 // in [0, Lc)
            const size_t oi = (size_t)b * Lc + l_out;
            out[oi]                    = o3;
            out[(size_t)Ltot + oi]     = o5;
            out[2 * (size_t)Ltot + oi] = o7;
        }
    }
}

extern "C" void kernel_launch(void* const* d_in, const int* in_sizes, int n_in,
                              void* d_out, int out_size) {
    const float* x   = (const float*)d_in[0];
    const float* aw3 = (const float*)d_in[1];
    const float* ab3 = (const float*)d_in[2];
    const float* cw3 = (const float*)d_in[3];
    const float* cb3 = (const float*)d_in[4];
    const float* aw5 = (const float*)d_in[5];
    const float* ab5 = (const float*)d_in[6];
    const float* cw5 = (const float*)d_in[7];
    const float* cb5 = (const float*)d_in[8];
    const float* aw7 = (const float*)d_in[9];
    const float* ab7 = (const float*)d_in[10];
    const float* cw7 = (const float*)d_in[11];
    const float* cb7 = (const float*)d_in[12];
    float* out = (float*)d_out;

    const int Bn   = in_sizes[0] / (Lc * Ec);   // 256
    const int Ltot = Bn * Lc;                    // B*L rows per output branch

    dim3 grid(2, Bn);   // 2 l-tiles of 250 outputs each, per batch row
    dim3 block(128);
    la_fused_kernel<<<grid, block>>>(x,
                                     aw3, ab3, cw3, cb3,
                                     aw5, ab5, cw5, cb5,
                                     aw7, ab7, cw7, cb7,
                                     out, Ltot);
}

// round 5
// speedup vs baseline: 1.9418x; 1.9418x over previous
#include <cuda_runtime.h>
#include <cstdint>

// LocalAttention fused kernel v2 (sm_103a).
// T[b,l,j] = dot(x[b,l,:], W[j,:]) for 18 rows (aw3:0-2, aw5:3-7, aw7:8-14, cw:15-17)
// out_k[b,l] = tanh( sigmoid(shifted-sum of T + ab_k) * T[.,dcol_k] + cb_k )
//
// v2 changes vs v1 (144us):
//  - x staged into shared via cp.async.cg double buffer (coalesced; zero-fill OOB)
//  - all operands loaded as ulonglong2 (f32x2 pairs) -> zero packing movs
//  - bank-swizzled x buffer; T buffer aliased over x buffers (54.4KB dyn smem)

typedef unsigned long long ull;

#define FMA2(d, a, b) \
    asm("fma.rn.f32x2 %0, %1, %2, %0;" : "+l"(d) : "l"(a), "l"(b))

__device__ __forceinline__ float unpk_sum(ull v) {
    float lo, hi;
    asm("mov.b64 {%0, %1}, %2;" : "=f"(lo), "=f"(hi) : "l"(v));
    return lo + hi;
}

__device__ __forceinline__ float sigm(float v) {
    return 1.0f / (1.0f + __expf(-v));
}

constexpr int Lc = 500;
constexpr int Ec = 300;
constexpr int E4 = 75;            // float4 per row
constexpr int POS = 256;          // positions per block (250 outputs + 6 halo)
constexpr int TL  = 250;
constexpr int NJ  = 18;
constexpr int CH  = 4;            // float4 per staged chunk
constexpr int NCHUNK = 19;        // ceil(75/4); last chunk zero-padded
constexpr int WPITCH = 304;       // floats per weight row (300 + 4 zero pad)
constexpr int XROW_W = 16;        // words per row in x buffer (CH float4)
constexpr int XBUF_W = POS * XROW_W;          // 4096 words = 16KB per buffer
constexpr int WS_OFF = 2 * XBUF_W;            // weights after the 2 x buffers
constexpr int SMEM_WORDS = 2 * XBUF_W + NJ * WPITCH;   // 13664 words
constexpr int SMEM_BYTES = SMEM_WORDS * 4;             // 54656 B

__global__ __launch_bounds__(128, 4)
void la_fused2(const float* __restrict__ x,
               const float* __restrict__ aw3, const float* __restrict__ ab3,
               const float* __restrict__ cw3, const float* __restrict__ cb3,
               const float* __restrict__ aw5, const float* __restrict__ ab5,
               const float* __restrict__ cw5, const float* __restrict__ cb5,
               const float* __restrict__ aw7, const float* __restrict__ ab7,
               const float* __restrict__ cw7, const float* __restrict__ cb7,
               float* __restrict__ out, int Ltot)
{
    extern __shared__ float sm[];
    float* ws = sm + WS_OFF;

    const int tid  = threadIdx.x;
    const int b    = blockIdx.y;
    const int tile = blockIdx.x;
    const int l_base = tile * TL - 3;
    const float* xrow0 = x + (size_t)b * Lc * Ec;

    // ---- weights -> shared (one-time; covered by first in-loop barrier) ----
    for (int i = tid; i < 3 * Ec; i += 128) ws[(     i / Ec) * WPITCH + (i % Ec)] = aw3[i];
    for (int i = tid; i < 5 * Ec; i += 128) ws[(3 +  i / Ec) * WPITCH + (i % Ec)] = aw5[i];
    for (int i = tid; i < 7 * Ec; i += 128) ws[(8 +  i / Ec) * WPITCH + (i % Ec)] = aw7[i];
    for (int i = tid; i < Ec; i += 128) {
        ws[15 * WPITCH + i] = cw3[i];
        ws[16 * WPITCH + i] = cw5[i];
        ws[17 * WPITCH + i] = cw7[i];
    }
    if (tid < NJ * 4) ws[(tid >> 2) * WPITCH + 300 + (tid & 3)] = 0.0f;  // zero pad col

    // shared base address for cp.async
    uint32_t sbase;
    asm("{ .reg .u64 t; cvta.to.shared.u64 t, %1; cvt.u32.u64 %0, t; }"
        : "=r"(sbase) : "l"(sm));

    // ---- stage chunk c of x into buffer buf (cp.async, zero-fill OOB) ----
    auto stage = [&](int c, int buf) {
        const uint32_t base = sbase + (uint32_t)buf * XBUF_W * 4;
        #pragma unroll
        for (int i = 0; i < 8; ++i) {
            int f = tid + i * 128;            // 0..1023 = 256 rows x 4 e
            int r = f >> 2;
            int e = f & 3;
            int l  = l_base + r;
            int eg = c * CH + e;
            bool v = (l >= 0) && (l < Lc) && (eg < E4);
            const float* g = xrow0 + (v ? ((size_t)l * Ec + eg * 4) : 0);
            uint32_t s = base + (uint32_t)(r * XROW_W + ((e ^ (r & 3)) << 2)) * 4;
            int sz = v ? 16 : 0;
            asm volatile("cp.async.cg.shared.global [%0], [%1], 16, %2;"
                         :: "r"(s), "l"(g), "r"(sz));
        }
        asm volatile("cp.async.commit_group;");
    };

    const int posA = tid, posB = tid + 128;

    ull accA[NJ], accB[NJ];
    #pragma unroll
    for (int j = 0; j < NJ; ++j) { accA[j] = 0ull; accB[j] = 0ull; }

    stage(0, 0);
    stage(1, 1);

    const int swA = (posA & 3), swB = (posB & 3);

    for (int c = 0; c < NCHUNK; ++c) {
        asm volatile("cp.async.wait_group 1;" ::: "memory");
        __syncthreads();

        const float* xb = sm + (c & 1) * XBUF_W;
        const float* wc = ws + (c * CH) * 4;          // &ws[j*WPITCH + eg*4] base

        #pragma unroll
        for (int e = 0; e < CH; ++e) {
            ulonglong2 xa = *(const ulonglong2*)(xb + posA * XROW_W + ((e ^ swA) << 2));
            ulonglong2 xv = *(const ulonglong2*)(xb + posB * XROW_W + ((e ^ swB) << 2));
            #pragma unroll
            for (int j = 0; j < NJ; ++j) {
                ulonglong2 wv = *(const ulonglong2*)(wc + j * WPITCH + e * 4);
                FMA2(accA[j], xa.x, wv.x);
                FMA2(accA[j], xa.y, wv.y);
                FMA2(accB[j], xv.x, wv.x);
                FMA2(accB[j], xv.y, wv.y);
            }
        }
        __syncthreads();
        if (c + 2 < NCHUNK) stage(c + 2, c & 1);
    }

    // ---- T buffer aliased over the (now dead) x buffers ----
    float* Tsh = sm;                                   // POS*19 words <= 8192
    #pragma unroll
    for (int j = 0; j < NJ; ++j) {
        Tsh[posA * 19 + j] = unpk_sum(accA[j]);
        Tsh[posB * 19 + j] = unpk_sum(accB[j]);
    }
    __syncthreads();

    // ---- epilogue ----
    const float sab3 = ab3[0], scb3 = cb3[0];
    const float sab5 = ab5[0], scb5 = cb5[0];
    const float sab7 = ab7[0], scb7 = cb7[0];

    #pragma unroll
    for (int half = 0; half < 2; ++half) {
        const int pos = tid + half * 128;
        if (pos >= 3 && pos <= 252) {
            const float* T0 = &Tsh[pos * 19];
            float s3 = Tsh[(pos - 1) * 19 + 0] + T0[1] + Tsh[(pos + 1) * 19 + 2];
            float s5 = 0.f;
            #pragma unroll
            for (int j = 0; j < 5; ++j) s5 += Tsh[(pos - 2 + j) * 19 + 3 + j];
            float s7 = 0.f;
            #pragma unroll
            for (int j = 0; j < 7; ++j) s7 += Tsh[(pos - 3 + j) * 19 + 8 + j];

            float o3 = tanhf(sigm(s3 + sab3) * T0[15] + scb3);
            float o5 = tanhf(sigm(s5 + sab5) * T0[16] + scb5);
            float o7 = tanhf(sigm(s7 + sab7) * T0[17] + scb7);

            const int l_out = l_base + pos;
            const size_t oi = (size_t)b * Lc + l_out;
            out[oi]                    = o3;
            out[(size_t)Ltot + oi]     = o5;
            out[2 * (size_t)Ltot + oi] = o7;
        }
    }
}

extern "C" void kernel_launch(void* const* d_in, const int* in_sizes, int n_in,
                              void* d_out, int out_size) {
    const float* x   = (const float*)d_in[0];
    const float* aw3 = (const float*)d_in[1];
    const float* ab3 = (const float*)d_in[2];
    const float* cw3 = (const float*)d_in[3];
    const float* cb3 = (const float*)d_in[4];
    const float* aw5 = (const float*)d_in[5];
    const float* ab5 = (const float*)d_in[6];
    const float* cw5 = (const float*)d_in[7];
    const float* cb5 = (const float*)d_in[8];
    const float* aw7 = (const float*)d_in[9];
    const float* ab7 = (const float*)d_in[10];
    const float* cw7 = (const float*)d_in[11];
    const float* cb7 = (const float*)d_in[12];
    float* out = (float*)d_out;

    const int Bn   = in_sizes[0] / (Lc * Ec);   // 256
    const int Ltot = Bn * Lc;

    static int smem_set = 0;
    if (!smem_set) {
        cudaFuncSetAttribute(la_fused2, cudaFuncAttributeMaxDynamicSharedMemorySize,
                             SMEM_BYTES);
        smem_set = 1;
    }

    dim3 grid(2, Bn);
    dim3 block(128);
    la_fused2<<<grid, block, SMEM_BYTES>>>(x,
                                           aw3, ab3, cw3, cb3,
                                           aw5, ab5, cw5, cb5,
                                           aw7, ab7, cw7, cb7,
                                           out, Ltot);
}